// round 11
// baseline (speedup 1.0000x reference)
#include <cuda_runtime.h>
#include <cuda_fp16.h>
#include <cstdint>
#include <cstddef>

#define B_  4
#define S_  2048
#define D_  1024
#define H_  16
#define DK_ 64
#define BH_ (B_ * H_)

// Scratch (allocation-free rule: __device__ globals).
__device__ __half g_Qh[BH_ * S_ * DK_];        // pre-scaled by log2(e)/sqrt(dk)
__device__ __half g_Kh[BH_ * S_ * DK_];
__device__ __half g_Vt[BH_ * DK_ * S_];        // [bh][feat][key] (transposed)
__device__ __half g_Oh[B_ * S_ * D_];          // attention output, fp16
__device__ __half g_Wh[3 * H_ * DK_ * DK_];    // fp16 W, SW128 smem-image layout
__device__ __half g_bh[3 * H_ * DK_];          // fp16 bias

// ---------------------------------------------------------------------------
// helpers
// ---------------------------------------------------------------------------
__device__ __forceinline__ uint32_t packh(float lo, float hi) {
    uint32_t r;
    asm("cvt.rn.f16x2.f32 %0, %1, %2;" : "=r"(r) : "f"(hi), "f"(lo));
    return r;
}
__device__ __forceinline__ void mma_f16(float* c,
                                        uint32_t a0, uint32_t a1,
                                        uint32_t a2, uint32_t a3,
                                        uint32_t b0, uint32_t b1) {
    asm volatile(
        "mma.sync.aligned.m16n8k16.row.col.f32.f16.f16.f32 "
        "{%0,%1,%2,%3}, {%4,%5,%6,%7}, {%8,%9}, {%0,%1,%2,%3};"
        : "+f"(c[0]), "+f"(c[1]), "+f"(c[2]), "+f"(c[3])
        : "r"(a0), "r"(a1), "r"(a2), "r"(a3), "r"(b0), "r"(b1));
}
#define LDMX4(r0, r1, r2, r3, a) \
    asm volatile("ldmatrix.sync.aligned.m8n8.x4.shared.b16 {%0,%1,%2,%3}, [%4];" \
                 : "=r"(r0), "=r"(r1), "=r"(r2), "=r"(r3) : "r"(a))
#define LDMX4T(r0, r1, r2, r3, a) \
    asm volatile("ldmatrix.sync.aligned.m8n8.x4.trans.shared.b16 {%0,%1,%2,%3}, [%4];" \
                 : "=r"(r0), "=r"(r1), "=r"(r2), "=r"(r3) : "r"(a))
__device__ __forceinline__ float ex2(float x) {
    float y; asm("ex2.approx.ftz.f32 %0, %1;" : "=f"(y) : "f"(x)); return y;
}
__device__ __forceinline__ uint32_t sptr(const void* p) {
    return (uint32_t)__cvta_generic_to_shared(p);
}
#define CP16(dst_u32, src_ptr) \
    asm volatile("cp.async.cg.shared.global [%0], [%1], 16;" \
                 :: "r"(dst_u32), "l"(src_ptr))
#define CP_COMMIT() asm volatile("cp.async.commit_group;")
#define CP_WAIT0()  asm volatile("cp.async.wait_group 0;" ::: "memory")

// ---------------------------------------------------------------------------
// Kernel 0: convert W -> fp16 in SW128 smem-image layout; bias -> fp16.
// ---------------------------------------------------------------------------
__global__ __launch_bounds__(128) void wprep_kernel(
    const float* __restrict__ Wq, const float* __restrict__ bq,
    const float* __restrict__ Wk, const float* __restrict__ bk,
    const float* __restrict__ Wv, const float* __restrict__ bv)
{
    const int h = blockIdx.x, p = blockIdx.y;
    const int tid = threadIdx.x;
    const float* Ws[3] = {Wq, Wk, Wv};
    const float* Bs[3] = {bq, bk, bv};

    const float* wsrc = Ws[p] + h * DK_ * DK_;
    char* wdst = reinterpret_cast<char*>(g_Wh) + ((size_t)p * H_ + h) * (DK_ * 128);
    #pragma unroll
    for (int n = 0; n < 4; ++n) {
        int i = tid + 128 * n;
        int r = i >> 3, c = i & 7;
        const float4* src = reinterpret_cast<const float4*>(wsrc + r * 64 + c * 8);
        float4 f0 = src[0], f1 = src[1];
        uint4 u;
        u.x = packh(f0.x, f0.y); u.y = packh(f0.z, f0.w);
        u.z = packh(f1.x, f1.y); u.w = packh(f1.z, f1.w);
        *reinterpret_cast<uint4*>(wdst + r * 128 + ((c * 16) ^ ((r & 7) * 16))) = u;
    }
    if (tid < DK_)
        g_bh[((size_t)p * H_ + h) * DK_ + tid] = __float2half(Bs[p][h * DK_ + tid]);
}

// ---------------------------------------------------------------------------
// Kernel 1: QKV projection, ONE projection p per CTA (occupancy-optimized).
// Grid (3 * BS/64, H), 128 threads; p = blockIdx.x % 3 (fastest-varying, so
// the 3 CTAs sharing an x slice are co-scheduled -> L2 hits on x).
// smem 16.5KB, ~70 regs -> ~7 resident CTAs (vs 4.5 before).
// ---------------------------------------------------------------------------
__global__ __launch_bounds__(128, 6) void qkv_proj_kernel(const float* __restrict__ x)
{
    __shared__ __align__(1024) char xs[64 * 128];
    __shared__ __align__(1024) char ws[64 * 128];
    __shared__ __align__(16)   __half sbias[DK_];

    const int bx   = blockIdx.x;
    const int p    = bx % 3;
    const int m0   = (bx / 3) * 64;
    const int h    = blockIdx.y;
    const int tid  = threadIdx.x;

    // Fire-and-forget: this p's W (8KB, pre-swizzled smem image) + bias.
    {
        const char* wsrc = reinterpret_cast<const char*>(g_Wh)
                         + ((size_t)p * H_ + h) * 8192;
        const uint32_t wb = sptr(ws);
        #pragma unroll
        for (int n = 0; n < 4; ++n) {
            int off = (tid + 128 * n) * 16;
            CP16(wb + off, wsrc + off);
        }
        if (tid < 8)
            CP16(sptr(sbias) + tid * 16,
                 reinterpret_cast<const char*>(g_bh) + ((size_t)p * H_ + h) * 128 + tid * 16);
        CP_COMMIT();
    }

    // x tile: convert fp32 -> fp16 SW128 (sync loads overlap W cp.async).
    #pragma unroll
    for (int n = 0; n < 4; ++n) {
        int i = tid + 128 * n;
        int r = i >> 3, c = i & 7;
        const float4* src = reinterpret_cast<const float4*>(
            x + (size_t)(m0 + r) * D_ + h * DK_ + c * 8);
        float4 f0 = src[0], f1 = src[1];
        uint4 u;
        u.x = packh(f0.x, f0.y); u.y = packh(f0.z, f0.w);
        u.z = packh(f1.x, f1.y); u.w = packh(f1.z, f1.w);
        *reinterpret_cast<uint4*>(xs + r * 128 + ((c * 16) ^ ((r & 7) * 16))) = u;
    }
    CP_WAIT0();
    __syncthreads();

    const int lane = tid & 31, warp = tid >> 5;
    const int g = lane >> 2, t = lane & 3;
    const int rr = lane & 7, qq = lane >> 3;
    const int r0 = warp * 16 + g, r1 = r0 + 8;

    // A fragments from x.
    uint32_t qa[4][4];
    {
        const uint32_t xb = sptr(xs);
        #pragma unroll
        for (int kt = 0; kt < 4; ++kt) {
            uint32_t addr = xb + (warp * 16 + rr + (qq & 1) * 8) * 128
                          + ((kt * 32 + (qq >> 1) * 16) ^ (rr * 16));
            LDMX4(qa[kt][0], qa[kt][1], qa[kt][2], qa[kt][3], addr);
        }
    }

    const int b  = m0 >> 11;
    const int s0 = m0 & (S_ - 1);
    const int bh = b * H_ + h;
    const float SCL = 0.18033688011112042f;   // log2(e)/sqrt(DK)

    const uint32_t wb = sptr(ws);
    float acc[8][4];
    #pragma unroll
    for (int nt = 0; nt < 8; ++nt)
        #pragma unroll
        for (int q = 0; q < 4; ++q) acc[nt][q] = 0.f;

    #pragma unroll
    for (int nt = 0; nt < 8; ++nt) {
        uint32_t a1 = wb + (8 * qq + rr) * 128 + ((nt * 16) ^ (rr * 16));
        uint32_t w0, w1, w2, w3, w4, w5, w6, w7;
        LDMX4T(w0, w1, w2, w3, a1);
        LDMX4T(w4, w5, w6, w7, a1 + 32 * 128);
        mma_f16(acc[nt], qa[0][0], qa[0][1], qa[0][2], qa[0][3], w0, w1);
        mma_f16(acc[nt], qa[1][0], qa[1][1], qa[1][2], qa[1][3], w2, w3);
        mma_f16(acc[nt], qa[2][0], qa[2][1], qa[2][2], qa[2][3], w4, w5);
        mma_f16(acc[nt], qa[3][0], qa[3][1], qa[3][2], qa[3][3], w6, w7);
    }

    if (p < 2) {
        __half* dst = (p == 0 ? g_Qh : g_Kh) + ((size_t)bh * S_ + s0) * DK_;
        const float mul = (p == 0) ? SCL : 1.0f;
        #pragma unroll
        for (int nt = 0; nt < 8; ++nt) {
            const int c0 = nt * 8 + 2 * t;
            float2 bb = __half22float2(
                *reinterpret_cast<const __half2*>(sbias + c0));
            *reinterpret_cast<uint32_t*>(dst + (size_t)r0 * DK_ + c0) =
                packh((acc[nt][0] + bb.x) * mul, (acc[nt][1] + bb.y) * mul);
            *reinterpret_cast<uint32_t*>(dst + (size_t)r1 * DK_ + c0) =
                packh((acc[nt][2] + bb.x) * mul, (acc[nt][3] + bb.y) * mul);
        }
    } else {
        // V transposed: g_Vt[bh][feat][key]
        #pragma unroll
        for (int nt = 0; nt < 8; ++nt) {
            const int c0 = nt * 8 + 2 * t;
            float2 bb = __half22float2(
                *reinterpret_cast<const __half2*>(sbias + c0));
            g_Vt[((size_t)bh * DK_ + c0)     * S_ + s0 + r0] = __float2half(acc[nt][0] + bb.x);
            g_Vt[((size_t)bh * DK_ + c0 + 1) * S_ + s0 + r0] = __float2half(acc[nt][1] + bb.y);
            g_Vt[((size_t)bh * DK_ + c0)     * S_ + s0 + r1] = __float2half(acc[nt][2] + bb.x);
            g_Vt[((size_t)bh * DK_ + c0 + 1) * S_ + s0 + r1] = __float2half(acc[nt][3] + bb.y);
        }
    }
}

// ---------------------------------------------------------------------------
// Kernel 2: fp16 flash attention (R10, unchanged), BM=128, BN=64, 256 thr.
// ---------------------------------------------------------------------------
__device__ __forceinline__ void stage_tile(uint32_t dst, const __half* src,
                                           int src_stride, int tid) {
    #pragma unroll
    for (int n = 0; n < 2; ++n) {
        int i = tid + 256 * n;
        int r = i >> 3, c = i & 7;
        CP16(dst + r * 128 + ((c * 16) ^ ((r & 7) * 16)),
             src + (size_t)r * src_stride + c * 8);
    }
}

__global__ __launch_bounds__(256, 2) void attn_kernel()
{
    __shared__ __align__(1024) char sk[2][64 * 128];
    __shared__ __align__(1024) char sv[2][64 * 128];

    const int it   = (gridDim.x - 1) - blockIdx.x;   // heavy tiles first
    const int bh   = blockIdx.y;
    const int tid  = threadIdx.x;
    const int lane = tid & 31, warp = tid >> 5;
    const int g    = lane >> 2, t = lane & 3;
    const int rr   = lane & 7,  qq = lane >> 3;
    const int r0   = warp * 16 + g, r1 = r0 + 8;

    const __half* Kb = g_Kh + (size_t)bh * S_ * DK_;
    const __half* Vb = g_Vt + (size_t)bh * DK_ * S_;

    stage_tile(sptr(sk[0]), Kb, DK_, tid);
    stage_tile(sptr(sv[0]), Vb, S_, tid);
    CP_COMMIT();

    const __half* Qp = g_Qh + ((size_t)bh * S_ + it * 128) * DK_;
    uint32_t qf[4][4];
    #pragma unroll
    for (int kt = 0; kt < 4; ++kt) {
        qf[kt][0] = *reinterpret_cast<const uint32_t*>(Qp + (size_t)r0 * DK_ + 16 * kt + 2 * t);
        qf[kt][1] = *reinterpret_cast<const uint32_t*>(Qp + (size_t)r1 * DK_ + 16 * kt + 2 * t);
        qf[kt][2] = *reinterpret_cast<const uint32_t*>(Qp + (size_t)r0 * DK_ + 16 * kt + 2 * t + 8);
        qf[kt][3] = *reinterpret_cast<const uint32_t*>(Qp + (size_t)r1 * DK_ + 16 * kt + 2 * t + 8);
    }

    const uint32_t offA = rr * 128 + ((qq * 16) ^ (rr * 16));
    const uint32_t offB = rr * 128 + ((64 + qq * 16) ^ (rr * 16));

    float m0 = -1e30f, m1 = -1e30f, l0 = 0.f, l1 = 0.f;
    float oacc[8][4];
    #pragma unroll
    for (int et = 0; et < 8; ++et)
        #pragma unroll
        for (int q = 0; q < 4; ++q) oacc[et][q] = 0.f;

    const int jtmax = 2 * it + 1;

    for (int jt = 0; jt <= jtmax; ++jt) {
        CP_WAIT0();
        __syncthreads();

        const int cur = jt & 1;
        if (jt < jtmax) {
            stage_tile(sptr(sk[cur ^ 1]), Kb + (size_t)(jt + 1) * 64 * DK_, DK_, tid);
            stage_tile(sptr(sv[cur ^ 1]), Vb + (jt + 1) * 64, S_, tid);
            CP_COMMIT();
        }

        if (warp < 4 && jt == jtmax) continue;   // fully masked corner

        const uint32_t kbase = sptr(sk[cur]);
        const uint32_t vbase = sptr(sv[cur]);

        float sacc[8][4];
        #pragma unroll
        for (int nt = 0; nt < 8; ++nt) {
            uint32_t k0, k1, k2, k3, k4, k5, k6, k7;
            LDMX4(k0, k1, k2, k3, kbase + nt * 1024 + offA);
            LDMX4(k4, k5, k6, k7, kbase + nt * 1024 + offB);
            #pragma unroll
            for (int q = 0; q < 4; ++q) sacc[nt][q] = 0.f;
            mma_f16(sacc[nt], qf[0][0], qf[0][1], qf[0][2], qf[0][3], k0, k1);
            mma_f16(sacc[nt], qf[1][0], qf[1][1], qf[1][2], qf[1][3], k2, k3);
            mma_f16(sacc[nt], qf[2][0], qf[2][1], qf[2][2], qf[2][3], k4, k5);
            mma_f16(sacc[nt], qf[3][0], qf[3][1], qf[3][2], qf[3][3], k6, k7);
        }

        const bool diag = (jt >= 2 * it);
        const int  coff = (jt - 2 * it) * 64;
        float rm0 = -1e30f, rm1 = -1e30f;
        #pragma unroll
        for (int nt = 0; nt < 8; ++nt) {
            const int c0 = nt * 8 + 2 * t;
            float v00 = sacc[nt][0], v01 = sacc[nt][1];
            float v10 = sacc[nt][2], v11 = sacc[nt][3];
            if (diag) {
                if (c0 + coff     > r0) v00 = -1e30f;
                if (c0 + 1 + coff > r0) v01 = -1e30f;
                if (c0 + coff     > r1) v10 = -1e30f;
                if (c0 + 1 + coff > r1) v11 = -1e30f;
            }
            sacc[nt][0] = v00; sacc[nt][1] = v01;
            sacc[nt][2] = v10; sacc[nt][3] = v11;
            rm0 = fmaxf(rm0, fmaxf(v00, v01));
            rm1 = fmaxf(rm1, fmaxf(v10, v11));
        }
        rm0 = fmaxf(rm0, __shfl_xor_sync(0xffffffffu, rm0, 1));
        rm0 = fmaxf(rm0, __shfl_xor_sync(0xffffffffu, rm0, 2));
        rm1 = fmaxf(rm1, __shfl_xor_sync(0xffffffffu, rm1, 1));
        rm1 = fmaxf(rm1, __shfl_xor_sync(0xffffffffu, rm1, 2));

        const float mn0 = fmaxf(m0, rm0), mn1 = fmaxf(m1, rm1);
        const float al0 = ex2(m0 - mn0), al1 = ex2(m1 - mn1);
        m0 = mn0; m1 = mn1;

        float rs0 = 0.f, rs1 = 0.f;
        #pragma unroll
        for (int nt = 0; nt < 8; ++nt) {
            float p00 = ex2(sacc[nt][0] - mn0);
            float p01 = ex2(sacc[nt][1] - mn0);
            float p10 = ex2(sacc[nt][2] - mn1);
            float p11 = ex2(sacc[nt][3] - mn1);
            sacc[nt][0] = p00; sacc[nt][1] = p01;
            sacc[nt][2] = p10; sacc[nt][3] = p11;
            rs0 += p00 + p01;
            rs1 += p10 + p11;
        }
        rs0 += __shfl_xor_sync(0xffffffffu, rs0, 1);
        rs0 += __shfl_xor_sync(0xffffffffu, rs0, 2);
        rs1 += __shfl_xor_sync(0xffffffffu, rs1, 1);
        rs1 += __shfl_xor_sync(0xffffffffu, rs1, 2);
        l0 = l0 * al0 + rs0;
        l1 = l1 * al1 + rs1;
        #pragma unroll
        for (int et = 0; et < 8; ++et) {
            oacc[et][0] *= al0; oacc[et][1] *= al0;
            oacc[et][2] *= al1; oacc[et][3] *= al1;
        }

        uint32_t pa[4][4];
        #pragma unroll
        for (int kt = 0; kt < 4; ++kt) {
            pa[kt][0] = packh(sacc[2 * kt][0],     sacc[2 * kt][1]);
            pa[kt][1] = packh(sacc[2 * kt][2],     sacc[2 * kt][3]);
            pa[kt][2] = packh(sacc[2 * kt + 1][0], sacc[2 * kt + 1][1]);
            pa[kt][3] = packh(sacc[2 * kt + 1][2], sacc[2 * kt + 1][3]);
        }

        #pragma unroll
        for (int nt = 0; nt < 8; ++nt) {
            uint32_t v0, v1, v2, v3, v4, v5, v6, v7;
            LDMX4(v0, v1, v2, v3, vbase + nt * 1024 + offA);
            LDMX4(v4, v5, v6, v7, vbase + nt * 1024 + offB);
            mma_f16(oacc[nt], pa[0][0], pa[0][1], pa[0][2], pa[0][3], v0, v1);
            mma_f16(oacc[nt], pa[1][0], pa[1][1], pa[1][2], pa[1][3], v2, v3);
            mma_f16(oacc[nt], pa[2][0], pa[2][1], pa[2][2], pa[2][3], v4, v5);
            mma_f16(oacc[nt], pa[3][0], pa[3][1], pa[3][2], pa[3][3], v6, v7);
        }
    }

    // Epilogue: normalize, write O (fp16) in [B,S,D] layout.
    const int b = bh >> 4, h = bh & 15;
    const float inv0 = 1.0f / l0, inv1 = 1.0f / l1;
    __half* d0 = g_Oh + (size_t)(b * S_ + it * 128 + r0) * D_ + h * DK_;
    __half* d1 = g_Oh + (size_t)(b * S_ + it * 128 + r1) * D_ + h * DK_;
    #pragma unroll
    for (int et = 0; et < 8; ++et) {
        const int c0 = et * 8 + 2 * t;
        *reinterpret_cast<uint32_t*>(d0 + c0) =
            packh(oacc[et][0] * inv0, oacc[et][1] * inv0);
        *reinterpret_cast<uint32_t*>(d1 + c0) =
            packh(oacc[et][2] * inv1, oacc[et][3] * inv1);
    }
}

// ---------------------------------------------------------------------------
// Kernel 3: residual + LayerNorm (fp16 O input). 128 thr x 8 elems per row.
// ---------------------------------------------------------------------------
__global__ __launch_bounds__(128) void ln_res_kernel(
    const float* __restrict__ x,
    const float* __restrict__ gamma,
    const float* __restrict__ beta,
    float* __restrict__ out)
{
    const int row = blockIdx.x;
    const int tid = threadIdx.x;

    uint4 op = reinterpret_cast<const uint4*>(g_Oh + (size_t)row * D_)[tid];
    const float4* xp = reinterpret_cast<const float4*>(x + (size_t)row * D_) + 2 * tid;
    float4 xv0 = xp[0], xv1 = xp[1];

    float2 o0 = __half22float2(*reinterpret_cast<__half2*>(&op.x));
    float2 o1 = __half22float2(*reinterpret_cast<__half2*>(&op.y));
    float2 o2 = __half22float2(*reinterpret_cast<__half2*>(&op.z));
    float2 o3 = __half22float2(*reinterpret_cast<__half2*>(&op.w));

    float y[8];
    y[0] = o0.x + xv0.x; y[1] = o0.y + xv0.y;
    y[2] = o1.x + xv0.z; y[3] = o1.y + xv0.w;
    y[4] = o2.x + xv1.x; y[5] = o2.y + xv1.y;
    y[6] = o3.x + xv1.z; y[7] = o3.y + xv1.w;

    float s = 0.f, ss = 0.f;
    #pragma unroll
    for (int i = 0; i < 8; ++i) { s += y[i]; ss += y[i] * y[i]; }
    #pragma unroll
    for (int off = 16; off; off >>= 1) {
        s  += __shfl_xor_sync(0xffffffffu, s,  off);
        ss += __shfl_xor_sync(0xffffffffu, ss, off);
    }

    __shared__ float red[8];
    __shared__ float mu_s, rs_s;
    const int wid = tid >> 5;
    if ((tid & 31) == 0) { red[wid] = s; red[wid + 4] = ss; }
    __syncthreads();
    if (tid == 0) {
        float S = 0.f, SS = 0.f;
        #pragma unroll
        for (int i = 0; i < 4; ++i) { S += red[i]; SS += red[i + 4]; }
        float mu  = S * (1.0f / D_);
        float var = SS * (1.0f / D_) - mu * mu;
        mu_s = mu;
        rs_s = rsqrtf(var + 1e-5f);
    }
    __syncthreads();

    const float mu = mu_s, rstd = rs_s;
    const float4* gp = reinterpret_cast<const float4*>(gamma) + 2 * tid;
    const float4* bp = reinterpret_cast<const float4*>(beta)  + 2 * tid;
    float4 gv0 = gp[0], gv1 = gp[1];
    float4 bv0 = bp[0], bv1 = bp[1];

    float4 r0, r1;
    r0.x = (y[0] - mu) * rstd * gv0.x + bv0.x;
    r0.y = (y[1] - mu) * rstd * gv0.y + bv0.y;
    r0.z = (y[2] - mu) * rstd * gv0.z + bv0.z;
    r0.w = (y[3] - mu) * rstd * gv0.w + bv0.w;
    r1.x = (y[4] - mu) * rstd * gv1.x + bv1.x;
    r1.y = (y[5] - mu) * rstd * gv1.y + bv1.y;
    r1.z = (y[6] - mu) * rstd * gv1.z + bv1.z;
    r1.w = (y[7] - mu) * rstd * gv1.w + bv1.w;
    float4* op2 = reinterpret_cast<float4*>(out + (size_t)row * D_) + 2 * tid;
    op2[0] = r0;
    op2[1] = r1;
}

// ---------------------------------------------------------------------------
extern "C" void kernel_launch(void* const* d_in, const int* in_sizes, int n_in,
                              void* d_out, int out_size)
{
    const float* x     = (const float*)d_in[0];
    const float* Wq    = (const float*)d_in[1];
    const float* bq    = (const float*)d_in[2];
    const float* Wk    = (const float*)d_in[3];
    const float* bk    = (const float*)d_in[4];
    const float* Wv    = (const float*)d_in[5];
    const float* bv    = (const float*)d_in[6];
    const float* gamma = (const float*)d_in[7];
    const float* beta  = (const float*)d_in[8];
    float* out = (float*)d_out;

    wprep_kernel<<<dim3(H_, 3), 128>>>(Wq, bq, Wk, bk, Wv, bv);
    qkv_proj_kernel<<<dim3(3 * (B_ * S_) / 64, H_), 128>>>(x);
    attn_kernel<<<dim3(S_ / 128, BH_), 256>>>();
    ln_res_kernel<<<B_ * S_, 128>>>(x, gamma, beta, out);
}

// round 12
// speedup vs baseline: 1.0493x; 1.0493x over previous
#include <cuda_runtime.h>
#include <cuda_fp16.h>
#include <cstdint>
#include <cstddef>

#define B_  4
#define S_  2048
#define D_  1024
#define H_  16
#define DK_ 64
#define BH_ (B_ * H_)

// Scratch (allocation-free rule: __device__ globals).
__device__ __half g_Kh[BH_ * S_ * DK_];
__device__ __half g_Vt[BH_ * DK_ * S_];        // [bh][feat][key] (transposed)
__device__ __half g_Oh[B_ * S_ * D_];          // attention output, fp16
__device__ __half g_Wh[3 * H_ * DK_ * DK_];    // fp16 W, SW128 smem-image layout
__device__ __half g_bh[3 * H_ * DK_];          // fp16 bias

// ---------------------------------------------------------------------------
// helpers
// ---------------------------------------------------------------------------
__device__ __forceinline__ uint32_t packh(float lo, float hi) {
    uint32_t r;
    asm("cvt.rn.f16x2.f32 %0, %1, %2;" : "=r"(r) : "f"(hi), "f"(lo));
    return r;
}
__device__ __forceinline__ void mma_f16(float* c,
                                        uint32_t a0, uint32_t a1,
                                        uint32_t a2, uint32_t a3,
                                        uint32_t b0, uint32_t b1) {
    asm volatile(
        "mma.sync.aligned.m16n8k16.row.col.f32.f16.f16.f32 "
        "{%0,%1,%2,%3}, {%4,%5,%6,%7}, {%8,%9}, {%0,%1,%2,%3};"
        : "+f"(c[0]), "+f"(c[1]), "+f"(c[2]), "+f"(c[3])
        : "r"(a0), "r"(a1), "r"(a2), "r"(a3), "r"(b0), "r"(b1));
}
#define LDMX4(r0, r1, r2, r3, a) \
    asm volatile("ldmatrix.sync.aligned.m8n8.x4.shared.b16 {%0,%1,%2,%3}, [%4];" \
                 : "=r"(r0), "=r"(r1), "=r"(r2), "=r"(r3) : "r"(a))
#define LDMX4T(r0, r1, r2, r3, a) \
    asm volatile("ldmatrix.sync.aligned.m8n8.x4.trans.shared.b16 {%0,%1,%2,%3}, [%4];" \
                 : "=r"(r0), "=r"(r1), "=r"(r2), "=r"(r3) : "r"(a))
__device__ __forceinline__ float ex2(float x) {
    float y; asm("ex2.approx.ftz.f32 %0, %1;" : "=f"(y) : "f"(x)); return y;
}
__device__ __forceinline__ uint32_t sptr(const void* p) {
    return (uint32_t)__cvta_generic_to_shared(p);
}
#define CP16(dst_u32, src_ptr) \
    asm volatile("cp.async.cg.shared.global [%0], [%1], 16;" \
                 :: "r"(dst_u32), "l"(src_ptr))
#define CP_COMMIT() asm volatile("cp.async.commit_group;")
#define CP_WAIT0()  asm volatile("cp.async.wait_group 0;" ::: "memory")

// ---------------------------------------------------------------------------
// Kernel 0: convert W -> fp16 in SW128 smem-image layout; bias -> fp16.
// ---------------------------------------------------------------------------
__global__ __launch_bounds__(128) void wprep_kernel(
    const float* __restrict__ Wq, const float* __restrict__ bq,
    const float* __restrict__ Wk, const float* __restrict__ bk,
    const float* __restrict__ Wv, const float* __restrict__ bv)
{
    const int h = blockIdx.x, p = blockIdx.y;
    const int tid = threadIdx.x;
    const float* Ws[3] = {Wq, Wk, Wv};
    const float* Bs[3] = {bq, bk, bv};

    const float* wsrc = Ws[p] + h * DK_ * DK_;
    char* wdst = reinterpret_cast<char*>(g_Wh) + ((size_t)p * H_ + h) * (DK_ * 128);
    #pragma unroll
    for (int n = 0; n < 4; ++n) {
        int i = tid + 128 * n;
        int r = i >> 3, c = i & 7;
        const float4* src = reinterpret_cast<const float4*>(wsrc + r * 64 + c * 8);
        float4 f0 = src[0], f1 = src[1];
        uint4 u;
        u.x = packh(f0.x, f0.y); u.y = packh(f0.z, f0.w);
        u.z = packh(f1.x, f1.y); u.w = packh(f1.z, f1.w);
        *reinterpret_cast<uint4*>(wdst + r * 128 + ((c * 16) ^ ((r & 7) * 16))) = u;
    }
    if (tid < DK_)
        g_bh[((size_t)p * H_ + h) * DK_ + tid] = __float2half(Bs[p][h * DK_ + tid]);
}

// ---------------------------------------------------------------------------
// Kernel 1: K/V projection only (Q is computed inside attention).
// Grid (BS/64, H), 128 threads. W (K,V) via linear cp.async from g_Wh.
// ---------------------------------------------------------------------------
__global__ __launch_bounds__(128) void kv_proj_kernel(const float* __restrict__ x)
{
    __shared__ __align__(1024) char xs[64 * 128];
    __shared__ __align__(1024) char ws[2][64 * 128];
    __shared__ __align__(16)   __half sbias[2 * DK_];

    const int h   = blockIdx.y;
    const int m0  = blockIdx.x * 64;
    const int tid = threadIdx.x;

    // Fire-and-forget: W_k + W_v (2 x 8KB, smem image) + their biases.
    {
        const char* wsrc = reinterpret_cast<const char*>(g_Wh);
        const uint32_t wb = sptr(ws[0]);
        #pragma unroll
        for (int n = 0; n < 8; ++n) {
            int i = tid + 128 * n;                 // 0..1023 (16B chunks)
            int p = 1 + (i >> 9);                  // 1 = K, 2 = V
            int off = (i & 511) * 16;
            CP16(wb + i * 16, wsrc + ((size_t)p * H_ + h) * 8192 + off);
        }
        if (tid < 16) {
            int p = 1 + (tid >> 3), c = tid & 7;
            CP16(sptr(sbias) + tid * 16,
                 reinterpret_cast<const char*>(g_bh) + ((size_t)p * H_ + h) * 128 + c * 16);
        }
        CP_COMMIT();
    }

    // x tile: convert fp32 -> fp16 SW128 (sync loads overlap W cp.async).
    #pragma unroll
    for (int n = 0; n < 4; ++n) {
        int i = tid + 128 * n;
        int r = i >> 3, c = i & 7;
        const float4* src = reinterpret_cast<const float4*>(
            x + (size_t)(m0 + r) * D_ + h * DK_ + c * 8);
        float4 f0 = src[0], f1 = src[1];
        uint4 u;
        u.x = packh(f0.x, f0.y); u.y = packh(f0.z, f0.w);
        u.z = packh(f1.x, f1.y); u.w = packh(f1.z, f1.w);
        *reinterpret_cast<uint4*>(xs + r * 128 + ((c * 16) ^ ((r & 7) * 16))) = u;
    }
    CP_WAIT0();
    __syncthreads();

    const int lane = tid & 31, warp = tid >> 5;
    const int g = lane >> 2, t = lane & 3;
    const int rr = lane & 7, qq = lane >> 3;
    const int r0 = warp * 16 + g, r1 = r0 + 8;

    // A fragments from x.
    uint32_t qa[4][4];
    {
        const uint32_t xb = sptr(xs);
        #pragma unroll
        for (int kt = 0; kt < 4; ++kt) {
            uint32_t addr = xb + (warp * 16 + rr + (qq & 1) * 8) * 128
                          + ((kt * 32 + (qq >> 1) * 16) ^ (rr * 16));
            LDMX4(qa[kt][0], qa[kt][1], qa[kt][2], qa[kt][3], addr);
        }
    }

    const int b  = m0 >> 11;
    const int s0 = m0 & (S_ - 1);
    const int bh = b * H_ + h;

    #pragma unroll
    for (int pp = 0; pp < 2; ++pp) {
        const uint32_t wb = sptr(ws[pp]);
        float acc[8][4];
        #pragma unroll
        for (int nt = 0; nt < 8; ++nt)
            #pragma unroll
            for (int q = 0; q < 4; ++q) acc[nt][q] = 0.f;

        #pragma unroll
        for (int nt = 0; nt < 8; ++nt) {
            uint32_t a1 = wb + (8 * qq + rr) * 128 + ((nt * 16) ^ (rr * 16));
            uint32_t w0, w1, w2, w3, w4, w5, w6, w7;
            LDMX4T(w0, w1, w2, w3, a1);
            LDMX4T(w4, w5, w6, w7, a1 + 32 * 128);
            mma_f16(acc[nt], qa[0][0], qa[0][1], qa[0][2], qa[0][3], w0, w1);
            mma_f16(acc[nt], qa[1][0], qa[1][1], qa[1][2], qa[1][3], w2, w3);
            mma_f16(acc[nt], qa[2][0], qa[2][1], qa[2][2], qa[2][3], w4, w5);
            mma_f16(acc[nt], qa[3][0], qa[3][1], qa[3][2], qa[3][3], w6, w7);
        }

        if (pp == 0) {
            __half* dst = g_Kh + ((size_t)bh * S_ + s0) * DK_;
            #pragma unroll
            for (int nt = 0; nt < 8; ++nt) {
                const int c0 = nt * 8 + 2 * t;
                float2 bb = __half22float2(
                    *reinterpret_cast<const __half2*>(sbias + c0));
                *reinterpret_cast<uint32_t*>(dst + (size_t)r0 * DK_ + c0) =
                    packh(acc[nt][0] + bb.x, acc[nt][1] + bb.y);
                *reinterpret_cast<uint32_t*>(dst + (size_t)r1 * DK_ + c0) =
                    packh(acc[nt][2] + bb.x, acc[nt][3] + bb.y);
            }
        } else {
            // V transposed: g_Vt[bh][feat][key]
            #pragma unroll
            for (int nt = 0; nt < 8; ++nt) {
                const int c0 = nt * 8 + 2 * t;
                float2 bb = __half22float2(
                    *reinterpret_cast<const __half2*>(sbias + DK_ + c0));
                g_Vt[((size_t)bh * DK_ + c0)     * S_ + s0 + r0] = __float2half(acc[nt][0] + bb.x);
                g_Vt[((size_t)bh * DK_ + c0 + 1) * S_ + s0 + r0] = __float2half(acc[nt][1] + bb.y);
                g_Vt[((size_t)bh * DK_ + c0)     * S_ + s0 + r1] = __float2half(acc[nt][2] + bb.x);
                g_Vt[((size_t)bh * DK_ + c0 + 1) * S_ + s0 + r1] = __float2half(acc[nt][3] + bb.y);
            }
        }
    }
}

// ---------------------------------------------------------------------------
// Kernel 2: fp16 flash attention with IN-KERNEL Q projection.
// Prologue: x (128 rows, head h) -> sk[1]+sv[1]; Wq -> sk[0] (cp.async);
// per-warp Q = x*Wq mma; (acc+bias)*SCL packs straight into qf A-fragments.
// Then the R10 loop runs unchanged (buffers reused by the K/V pipeline).
// ---------------------------------------------------------------------------
__device__ __forceinline__ void stage_tile(uint32_t dst, const __half* src,
                                           int src_stride, int tid) {
    #pragma unroll
    for (int n = 0; n < 2; ++n) {
        int i = tid + 256 * n;
        int r = i >> 3, c = i & 7;
        CP16(dst + r * 128 + ((c * 16) ^ ((r & 7) * 16)),
             src + (size_t)r * src_stride + c * 8);
    }
}

__global__ __launch_bounds__(256, 2) void attn_kernel(const float* __restrict__ x)
{
    __shared__ __align__(1024) char sk[2][64 * 128];
    __shared__ __align__(1024) char sv[2][64 * 128];

    const int it   = (gridDim.x - 1) - blockIdx.x;   // heavy tiles first
    const int bh   = blockIdx.y;
    const int tid  = threadIdx.x;
    const int lane = tid & 31, warp = tid >> 5;
    const int g    = lane >> 2, t = lane & 3;
    const int rr   = lane & 7,  qq = lane >> 3;
    const int r0   = warp * 16 + g, r1 = r0 + 8;
    const int b    = bh >> 4, h = bh & 15;

    // ---- Prologue: in-kernel Q projection ----
    // Wq (pre-swizzled smem image) -> sk[0] via cp.async.
    {
        const char* wsrc = reinterpret_cast<const char*>(g_Wh) + (size_t)h * 8192;
        const uint32_t wb = sptr(sk[0]);
        #pragma unroll
        for (int n = 0; n < 2; ++n) {
            int off = (tid + 256 * n) * 16;
            CP16(wb + off, wsrc + off);
        }
        CP_COMMIT();
    }
    // x tile (128 rows of head h) -> sk[1] (rows 0-63) + sv[1] (rows 64-127).
    {
        const size_t xrow0 = (size_t)(b * S_ + it * 128);
        #pragma unroll
        for (int n = 0; n < 4; ++n) {
            int i = tid + 256 * n;
            int r = i >> 3, c = i & 7;
            const float4* src = reinterpret_cast<const float4*>(
                x + (xrow0 + r) * D_ + h * DK_ + c * 8);
            float4 f0 = src[0], f1 = src[1];
            uint4 u;
            u.x = packh(f0.x, f0.y); u.y = packh(f0.z, f0.w);
            u.z = packh(f1.x, f1.y); u.w = packh(f1.z, f1.w);
            char* dstb = (r < 64) ? sk[1] : sv[1];
            *reinterpret_cast<uint4*>(dstb + (r & 63) * 128
                                      + ((c * 16) ^ ((r & 7) * 16))) = u;
        }
    }
    CP_WAIT0();
    __syncthreads();

    const float SCL = 0.18033688011112042f;  // log2(e)/sqrt(DK)
    uint32_t qf[4][4];
    {
        // A fragments of x (this warp's 16 rows).
        const uint32_t xb = sptr(warp < 4 ? sk[1] : sv[1]);
        const int xrb = (warp * 16) & 63;
        uint32_t xa[4][4];
        #pragma unroll
        for (int kt = 0; kt < 4; ++kt) {
            uint32_t addr = xb + (xrb + rr + (qq & 1) * 8) * 128
                          + ((kt * 32 + (qq >> 1) * 16) ^ (rr * 16));
            LDMX4(xa[kt][0], xa[kt][1], xa[kt][2], xa[kt][3], addr);
        }
        // Q = x * Wq  (C-fragments == QK A-fragment layout)
        const uint32_t wb = sptr(sk[0]);
        float accq[8][4];
        #pragma unroll
        for (int nt = 0; nt < 8; ++nt)
            #pragma unroll
            for (int q = 0; q < 4; ++q) accq[nt][q] = 0.f;
        #pragma unroll
        for (int nt = 0; nt < 8; ++nt) {
            uint32_t a1 = wb + (8 * qq + rr) * 128 + ((nt * 16) ^ (rr * 16));
            uint32_t w0, w1, w2, w3, w4, w5, w6, w7;
            LDMX4T(w0, w1, w2, w3, a1);
            LDMX4T(w4, w5, w6, w7, a1 + 32 * 128);
            mma_f16(accq[nt], xa[0][0], xa[0][1], xa[0][2], xa[0][3], w0, w1);
            mma_f16(accq[nt], xa[1][0], xa[1][1], xa[1][2], xa[1][3], w2, w3);
            mma_f16(accq[nt], xa[2][0], xa[2][1], xa[2][2], xa[2][3], w4, w5);
            mma_f16(accq[nt], xa[3][0], xa[3][1], xa[3][2], xa[3][3], w6, w7);
        }
        // (acc + bias) * SCL -> fp16 A-fragments.
        const __half* bq = g_bh + h * DK_;
        #pragma unroll
        for (int kt = 0; kt < 4; ++kt) {
            const int c0 = (2 * kt) * 8 + 2 * t;
            const int c1 = (2 * kt + 1) * 8 + 2 * t;
            float2 b0 = __half22float2(*reinterpret_cast<const __half2*>(bq + c0));
            float2 b1 = __half22float2(*reinterpret_cast<const __half2*>(bq + c1));
            qf[kt][0] = packh((accq[2*kt][0] + b0.x) * SCL, (accq[2*kt][1] + b0.y) * SCL);
            qf[kt][1] = packh((accq[2*kt][2] + b0.x) * SCL, (accq[2*kt][3] + b0.y) * SCL);
            qf[kt][2] = packh((accq[2*kt+1][0] + b1.x) * SCL, (accq[2*kt+1][1] + b1.y) * SCL);
            qf[kt][3] = packh((accq[2*kt+1][2] + b1.x) * SCL, (accq[2*kt+1][3] + b1.y) * SCL);
        }
    }
    __syncthreads();   // all warps done reading sk[0]/sk[1]/sv[1]

    const __half* Kb = g_Kh + (size_t)bh * S_ * DK_;
    const __half* Vb = g_Vt + (size_t)bh * DK_ * S_;

    // Stage kv-tile 0 (overwrites Wq buffer).
    stage_tile(sptr(sk[0]), Kb, DK_, tid);
    stage_tile(sptr(sv[0]), Vb, S_, tid);
    CP_COMMIT();

    const uint32_t offA = rr * 128 + ((qq * 16) ^ (rr * 16));
    const uint32_t offB = rr * 128 + ((64 + qq * 16) ^ (rr * 16));

    float m0 = -1e30f, m1 = -1e30f, l0 = 0.f, l1 = 0.f;
    float oacc[8][4];
    #pragma unroll
    for (int et = 0; et < 8; ++et)
        #pragma unroll
        for (int q = 0; q < 4; ++q) oacc[et][q] = 0.f;

    const int jtmax = 2 * it + 1;

    for (int jt = 0; jt <= jtmax; ++jt) {
        CP_WAIT0();
        __syncthreads();

        const int cur = jt & 1;
        if (jt < jtmax) {
            stage_tile(sptr(sk[cur ^ 1]), Kb + (size_t)(jt + 1) * 64 * DK_, DK_, tid);
            stage_tile(sptr(sv[cur ^ 1]), Vb + (jt + 1) * 64, S_, tid);
            CP_COMMIT();
        }

        if (warp < 4 && jt == jtmax) continue;   // fully masked corner

        const uint32_t kbase = sptr(sk[cur]);
        const uint32_t vbase = sptr(sv[cur]);

        float sacc[8][4];
        #pragma unroll
        for (int nt = 0; nt < 8; ++nt) {
            uint32_t k0, k1, k2, k3, k4, k5, k6, k7;
            LDMX4(k0, k1, k2, k3, kbase + nt * 1024 + offA);
            LDMX4(k4, k5, k6, k7, kbase + nt * 1024 + offB);
            #pragma unroll
            for (int q = 0; q < 4; ++q) sacc[nt][q] = 0.f;
            mma_f16(sacc[nt], qf[0][0], qf[0][1], qf[0][2], qf[0][3], k0, k1);
            mma_f16(sacc[nt], qf[1][0], qf[1][1], qf[1][2], qf[1][3], k2, k3);
            mma_f16(sacc[nt], qf[2][0], qf[2][1], qf[2][2], qf[2][3], k4, k5);
            mma_f16(sacc[nt], qf[3][0], qf[3][1], qf[3][2], qf[3][3], k6, k7);
        }

        const bool diag = (jt >= 2 * it);
        const int  coff = (jt - 2 * it) * 64;
        float rm0 = -1e30f, rm1 = -1e30f;
        #pragma unroll
        for (int nt = 0; nt < 8; ++nt) {
            const int c0 = nt * 8 + 2 * t;
            float v00 = sacc[nt][0], v01 = sacc[nt][1];
            float v10 = sacc[nt][2], v11 = sacc[nt][3];
            if (diag) {
                if (c0 + coff     > r0) v00 = -1e30f;
                if (c0 + 1 + coff > r0) v01 = -1e30f;
                if (c0 + coff     > r1) v10 = -1e30f;
                if (c0 + 1 + coff > r1) v11 = -1e30f;
            }
            sacc[nt][0] = v00; sacc[nt][1] = v01;
            sacc[nt][2] = v10; sacc[nt][3] = v11;
            rm0 = fmaxf(rm0, fmaxf(v00, v01));
            rm1 = fmaxf(rm1, fmaxf(v10, v11));
        }
        rm0 = fmaxf(rm0, __shfl_xor_sync(0xffffffffu, rm0, 1));
        rm0 = fmaxf(rm0, __shfl_xor_sync(0xffffffffu, rm0, 2));
        rm1 = fmaxf(rm1, __shfl_xor_sync(0xffffffffu, rm1, 1));
        rm1 = fmaxf(rm1, __shfl_xor_sync(0xffffffffu, rm1, 2));

        const float mn0 = fmaxf(m0, rm0), mn1 = fmaxf(m1, rm1);
        const float al0 = ex2(m0 - mn0), al1 = ex2(m1 - mn1);
        m0 = mn0; m1 = mn1;

        float rs0 = 0.f, rs1 = 0.f;
        #pragma unroll
        for (int nt = 0; nt < 8; ++nt) {
            float p00 = ex2(sacc[nt][0] - mn0);
            float p01 = ex2(sacc[nt][1] - mn0);
            float p10 = ex2(sacc[nt][2] - mn1);
            float p11 = ex2(sacc[nt][3] - mn1);
            sacc[nt][0] = p00; sacc[nt][1] = p01;
            sacc[nt][2] = p10; sacc[nt][3] = p11;
            rs0 += p00 + p01;
            rs1 += p10 + p11;
        }
        rs0 += __shfl_xor_sync(0xffffffffu, rs0, 1);
        rs0 += __shfl_xor_sync(0xffffffffu, rs0, 2);
        rs1 += __shfl_xor_sync(0xffffffffu, rs1, 1);
        rs1 += __shfl_xor_sync(0xffffffffu, rs1, 2);
        l0 = l0 * al0 + rs0;
        l1 = l1 * al1 + rs1;
        #pragma unroll
        for (int et = 0; et < 8; ++et) {
            oacc[et][0] *= al0; oacc[et][1] *= al0;
            oacc[et][2] *= al1; oacc[et][3] *= al1;
        }

        uint32_t pa[4][4];
        #pragma unroll
        for (int kt = 0; kt < 4; ++kt) {
            pa[kt][0] = packh(sacc[2 * kt][0],     sacc[2 * kt][1]);
            pa[kt][1] = packh(sacc[2 * kt][2],     sacc[2 * kt][3]);
            pa[kt][2] = packh(sacc[2 * kt + 1][0], sacc[2 * kt + 1][1]);
            pa[kt][3] = packh(sacc[2 * kt + 1][2], sacc[2 * kt + 1][3]);
        }

        #pragma unroll
        for (int nt = 0; nt < 8; ++nt) {
            uint32_t v0, v1, v2, v3, v4, v5, v6, v7;
            LDMX4(v0, v1, v2, v3, vbase + nt * 1024 + offA);
            LDMX4(v4, v5, v6, v7, vbase + nt * 1024 + offB);
            mma_f16(oacc[nt], pa[0][0], pa[0][1], pa[0][2], pa[0][3], v0, v1);
            mma_f16(oacc[nt], pa[1][0], pa[1][1], pa[1][2], pa[1][3], v2, v3);
            mma_f16(oacc[nt], pa[2][0], pa[2][1], pa[2][2], pa[2][3], v4, v5);
            mma_f16(oacc[nt], pa[3][0], pa[3][1], pa[3][2], pa[3][3], v6, v7);
        }
    }

    // Epilogue: normalize, write O (fp16) in [B,S,D] layout.
    const float inv0 = 1.0f / l0, inv1 = 1.0f / l1;
    __half* d0 = g_Oh + (size_t)(b * S_ + it * 128 + r0) * D_ + h * DK_;
    __half* d1 = g_Oh + (size_t)(b * S_ + it * 128 + r1) * D_ + h * DK_;
    #pragma unroll
    for (int et = 0; et < 8; ++et) {
        const int c0 = et * 8 + 2 * t;
        *reinterpret_cast<uint32_t*>(d0 + c0) =
            packh(oacc[et][0] * inv0, oacc[et][1] * inv0);
        *reinterpret_cast<uint32_t*>(d1 + c0) =
            packh(oacc[et][2] * inv1, oacc[et][3] * inv1);
    }
}

// ---------------------------------------------------------------------------
// Kernel 3: residual + LayerNorm (fp16 O input). R10-proven: 256 thr/row.
// ---------------------------------------------------------------------------
__global__ __launch_bounds__(256) void ln_res_kernel(
    const float* __restrict__ x,
    const float* __restrict__ gamma,
    const float* __restrict__ beta,
    float* __restrict__ out)
{
    const int row = blockIdx.x;
    const int tid = threadIdx.x;

    uint2 op = reinterpret_cast<const uint2*>(g_Oh + (size_t)row * D_)[tid];
    float2 o01 = __half22float2(*reinterpret_cast<__half2*>(&op.x));
    float2 o23 = __half22float2(*reinterpret_cast<__half2*>(&op.y));
    float4 xv = reinterpret_cast<const float4*>(x + (size_t)row * D_)[tid];
    float4 y;
    y.x = o01.x + xv.x; y.y = o01.y + xv.y;
    y.z = o23.x + xv.z; y.w = o23.y + xv.w;

    float s  = y.x + y.y + y.z + y.w;
    float ss = y.x * y.x + y.y * y.y + y.z * y.z + y.w * y.w;
    #pragma unroll
    for (int off = 16; off; off >>= 1) {
        s  += __shfl_xor_sync(0xffffffffu, s,  off);
        ss += __shfl_xor_sync(0xffffffffu, ss, off);
    }

    __shared__ float red[16];
    __shared__ float mu_s, rs_s;
    const int wid = tid >> 5;
    if ((tid & 31) == 0) { red[wid] = s; red[wid + 8] = ss; }
    __syncthreads();
    if (tid == 0) {
        float S = 0.f, SS = 0.f;
        #pragma unroll
        for (int i = 0; i < 8; ++i) { S += red[i]; SS += red[i + 8]; }
        float mu  = S * (1.0f / D_);
        float var = SS * (1.0f / D_) - mu * mu;
        mu_s = mu;
        rs_s = rsqrtf(var + 1e-5f);
    }
    __syncthreads();

    const float mu = mu_s, rstd = rs_s;
    float4 gv = reinterpret_cast<const float4*>(gamma)[tid];
    float4 bv = reinterpret_cast<const float4*>(beta)[tid];
    float4 r;
    r.x = (y.x - mu) * rstd * gv.x + bv.x;
    r.y = (y.y - mu) * rstd * gv.y + bv.y;
    r.z = (y.z - mu) * rstd * gv.z + bv.z;
    r.w = (y.w - mu) * rstd * gv.w + bv.w;
    reinterpret_cast<float4*>(out + (size_t)row * D_)[tid] = r;
}

// ---------------------------------------------------------------------------
extern "C" void kernel_launch(void* const* d_in, const int* in_sizes, int n_in,
                              void* d_out, int out_size)
{
    const float* x     = (const float*)d_in[0];
    const float* Wq    = (const float*)d_in[1];
    const float* bq    = (const float*)d_in[2];
    const float* Wk    = (const float*)d_in[3];
    const float* bk    = (const float*)d_in[4];
    const float* Wv    = (const float*)d_in[5];
    const float* bv    = (const float*)d_in[6];
    const float* gamma = (const float*)d_in[7];
    const float* beta  = (const float*)d_in[8];
    float* out = (float*)d_out;

    wprep_kernel<<<dim3(H_, 3), 128>>>(Wq, bq, Wk, bk, Wv, bv);
    kv_proj_kernel<<<dim3((B_ * S_) / 64, H_), 128>>>(x);
    attn_kernel<<<dim3(S_ / 128, BH_), 256>>>(x);
    ln_res_kernel<<<B_ * S_, 256>>>(x, gamma, beta, out);
}